// round 2
// baseline (speedup 1.0000x reference)
#include <cuda_runtime.h>
#include <math.h>

#define HH 640
#define WW 640
#define MHH 40
#define MWW 40
#define NC 8
#define NB 4
#define KPER 400

#define TILE 32
#define PLANE (34*35)              // 34 rows, stride 35 (bank-conflict-free)
#define SMEM_FLOATS (16*PLANE + 8*8*9*2)
#define SMEM_BYTES (SMEM_FLOATS*4)

// scratch ping-pong buffers, planar layout [b][c][comp][H][W]
__device__ float g_bufA[NB*NC*2*HH*WW];
__device__ float g_bufB[NB*NC*2*HH*WW];
__device__ float g_bm[NB*MHH*MWW];

// ---------------------------------------------------------------------------
// Mask generation: sigmoid(s_b * w_eff), exact k-th largest (binary search on
// float bits), binarize. One block per batch.
// ---------------------------------------------------------------------------
__global__ void mask_kernel(const float* __restrict__ my1,
                            const float* __restrict__ wmask,
                            float* __restrict__ out_bin, int write_bin) {
    __shared__ float s_sig[MHH*MWW];
    __shared__ int s_cnt;
    int b = blockIdx.x, tid = threadIdx.x;
    float sb = my1[b];
    for (int i = tid; i < MHH*MWW; i += blockDim.x) {
        int col = i % MWW;
        float wv = (col >= 18 && col < 23) ? 1e7f : wmask[i];
        s_sig[i] = 1.0f / (1.0f + expf(-sb * wv));
    }
    __syncthreads();
    // binary search over positive-float bit space for 400th largest value
    unsigned lo = 0u, hi = 0x3F800001u;   // values in (0, 1.0]
    while (hi - lo > 1u) {
        unsigned mid = (lo + hi) >> 1;
        float t = __uint_as_float(mid);
        if (tid == 0) s_cnt = 0;
        __syncthreads();
        int c = 0;
        for (int i = tid; i < MHH*MWW; i += blockDim.x)
            c += (s_sig[i] >= t) ? 1 : 0;
        atomicAdd(&s_cnt, c);
        __syncthreads();
        int tot = s_cnt;
        __syncthreads();
        if (tot >= KPER) lo = mid; else hi = mid;
    }
    float thr = __uint_as_float(lo);
    for (int i = tid; i < MHH*MWW; i += blockDim.x) {
        // kept iff sig >= thr; then probs=(sig+1)/2 > 0.5 -> hard = 1
        float v = (s_sig[i] >= thr) ? 1.0f : 0.0f;
        g_bm[b*MHH*MWW + i] = v;
        if (write_bin) out_bin[b*MHH*MWW + i] = v;
    }
}

// ---------------------------------------------------------------------------
// pred0 = m ? x : 0, interleaved -> planar
// ---------------------------------------------------------------------------
__global__ void init_kernel(const float2* __restrict__ x, float* __restrict__ dst) {
    int idx = blockIdx.x * blockDim.x + threadIdx.x;  // over B*NC*H*W
    if (idx >= NB*NC*HH*WW) return;
    int hw = idx % (HH*WW);
    int w = hw % WW, h = hw / WW;
    int bc = idx / (HH*WW);
    int b = bc >> 3;
    float m = g_bm[b*MHH*MWW + (h % MHH)*MWW + (w % MWW)];
    float2 v = x[idx];
    float vr = (m != 0.0f) ? v.x : 0.0f;
    float vi = (m != 0.0f) ? v.y : 0.0f;
    int basep = (bc*2)*HH*WW + hw;
    dst[basep] = vr;
    dst[basep + HH*WW] = vi;
}

// ---------------------------------------------------------------------------
// mask_adj = tile(binary_mask) -> d_out
// ---------------------------------------------------------------------------
__global__ void maskadj_kernel(float* __restrict__ out) {
    int idx = blockIdx.x * blockDim.x + threadIdx.x;  // over B*H*W
    if (idx >= NB*HH*WW) return;
    int w = idx % WW, h = (idx / WW) % HH, b = idx / (HH*WW);
    out[idx] = g_bm[b*MHH*MWW + (h % MHH)*MWW + (w % MWW)];
}

// ---------------------------------------------------------------------------
// Complex 3x3 conv (center tap zeroed) + data consistency.
// MODE 0: write planar scratch. MODE 1: write interleaved float2 to d_out.
// Block: 256 threads = 32 cols x 8 row-groups; each thread: 4 rows x 8 cout.
// ---------------------------------------------------------------------------
template<int MODE>
__global__ void __launch_bounds__(256, 2)
conv_kernel(const float* __restrict__ src, float* __restrict__ dst,
            const float* __restrict__ wr_g, const float* __restrict__ wi_g) {
    extern __shared__ float smem[];
    float* s_in = smem;                 // 16 planes of 34x(stride 35)
    float* s_w  = smem + 16*PLANE;      // [ci][co][tap][2]

    const int tid = threadIdx.x;
    const int b  = blockIdx.z;
    const int x0 = blockIdx.x * TILE;
    const int y0 = blockIdx.y * TILE;

    // load input tile: 16 planes, halo of 1, zero padding at borders
    for (int p = 0; p < 16; p++) {
        const float* sp = src + ((b*NC + (p >> 1))*2 + (p & 1))*HH*WW;
        float* dp = s_in + p*PLANE;
        for (int idx = tid; idx < 34*34; idx += 256) {
            int r = idx / 34, c = idx - r*34;
            int gh = y0 - 1 + r, gw = x0 - 1 + c;
            float v = 0.0f;
            if (gh >= 0 && gh < HH && gw >= 0 && gw < WW) v = sp[gh*WW + gw];
            dp[r*35 + c] = v;
        }
    }
    // load weights (center tap zeroed): s_w[ci*144 + co*18 + t*2 + {0,1}]
    for (int j = tid; j < 576; j += 256) {
        int t = j % 9, co = (j / 9) & 7, ci = j / 72;
        float vr = 0.0f, vi = 0.0f;
        if (t != 4) {
            vr = wr_g[(co*8 + ci)*9 + t];
            vi = wi_g[(co*8 + ci)*9 + t];
        }
        s_w[ci*144 + co*18 + t*2]     = vr;
        s_w[ci*144 + co*18 + t*2 + 1] = vi;
    }
    __syncthreads();

    const int tx = tid & 31, ty = tid >> 5;
    const int row0 = ty * 4;

    float accr[8][4], acci[8][4];
#pragma unroll
    for (int co = 0; co < 8; co++)
#pragma unroll
        for (int p = 0; p < 4; p++) { accr[co][p] = 0.0f; acci[co][p] = 0.0f; }

#pragma unroll 1
    for (int ci = 0; ci < 8; ci++) {
        const float* pr = s_in + (ci*2)*PLANE + row0*35 + tx;
        const float* pi = pr + PLANE;
        float tr[6][3], ti[6][3];
#pragma unroll
        for (int r = 0; r < 6; r++)
#pragma unroll
            for (int c = 0; c < 3; c++) {
                tr[r][c] = pr[r*35 + c];
                ti[r][c] = pi[r*35 + c];
            }
        const float* wp = s_w + ci*144;
#pragma unroll
        for (int co = 0; co < 8; co++) {
#pragma unroll
            for (int t = 0; t < 9; t++) {
                float wr = wp[co*18 + 2*t];
                float wi = wp[co*18 + 2*t + 1];
                int ky = t / 3, kx = t - ky*3;
#pragma unroll
                for (int p = 0; p < 4; p++) {
                    float xr = tr[p + ky][kx], xi = ti[p + ky][kx];
                    accr[co][p] = fmaf(xr,  wr, accr[co][p]);
                    accr[co][p] = fmaf(-xi, wi, accr[co][p]);
                    acci[co][p] = fmaf(xi,  wr, acci[co][p]);
                    acci[co][p] = fmaf(xr,  wi, acci[co][p]);
                }
            }
        }
    }

    const int ow = x0 + tx;
#pragma unroll
    for (int p = 0; p < 4; p++) {
        const int oh = y0 + row0 + p;
        const float m = g_bm[b*MHH*MWW + (oh % MHH)*MWW + (ow % MWW)];
        const bool keep = (m != 0.0f);
#pragma unroll
        for (int co = 0; co < 8; co++) {
            float vr = accr[co][p], vi = acci[co][p];
            if (keep) {
                // invariant: at m==1, pred_prev == x; center is in smem
                vr = s_in[(co*2  )*PLANE + (row0 + p + 1)*35 + (tx + 1)];
                vi = s_in[(co*2+1)*PLANE + (row0 + p + 1)*35 + (tx + 1)];
            }
            if (MODE == 0) {
                int basep = ((b*NC + co)*2)*HH*WW + oh*WW + ow;
                dst[basep] = vr;
                dst[basep + HH*WW] = vi;
            } else {
                float2 v; v.x = vr; v.y = vi;
                ((float2*)dst)[((b*NC + co)*HH + oh)*WW + ow] = v;
            }
        }
    }
}

// ---------------------------------------------------------------------------
extern "C" void kernel_launch(void* const* d_in, const int* in_sizes, int n_in,
                              void* d_out, int out_size) {
    const float* x     = (const float*)d_in[0];   // [4,8,640,640,2]
    const float* my1   = (const float*)d_in[1];   // [4,1,1,1]
    const float* wmask = (const float*)d_in[2];   // [1,1,40,40]
    const float* wr    = (const float*)d_in[3];   // [4,8,8,3,3]
    const float* wi    = (const float*)d_in[4];   // [4,8,8,3,3]
    float* out = (float*)d_out;

    void *pA, *pB;
    cudaGetSymbolAddress(&pA, g_bufA);
    cudaGetSymbolAddress(&pB, g_bufB);
    float* bufA = (float*)pA;
    float* bufB = (float*)pB;

    const int PRED = NB*NC*HH*WW*2;        // 26,214,400
    const int MADJ = NB*HH*WW;             // 1,638,400
    const int BINM = NB*MHH*MWW;           // 6,400
    int has_extra = (out_size >= PRED + MADJ + BINM) ? 1 : 0;
    float* out_bin = has_extra ? out + PRED + MADJ : nullptr;

    cudaFuncSetAttribute(conv_kernel<0>, cudaFuncAttributeMaxDynamicSharedMemorySize, SMEM_BYTES);
    cudaFuncSetAttribute(conv_kernel<1>, cudaFuncAttributeMaxDynamicSharedMemorySize, SMEM_BYTES);

    mask_kernel<<<NB, 256>>>(my1, wmask, out_bin, has_extra);
    init_kernel<<<(NB*NC*HH*WW + 255)/256, 256>>>((const float2*)x, bufA);
    if (has_extra)
        maskadj_kernel<<<(NB*HH*WW + 255)/256, 256>>>(out + PRED);

    dim3 grid(WW/TILE, HH/TILE, NB);  // 20 x 20 x 4
    conv_kernel<0><<<grid, 256, SMEM_BYTES>>>(bufA, bufB, wr,        wi);
    conv_kernel<0><<<grid, 256, SMEM_BYTES>>>(bufB, bufA, wr + 576,  wi + 576);
    conv_kernel<0><<<grid, 256, SMEM_BYTES>>>(bufA, bufB, wr + 1152, wi + 1152);
    conv_kernel<1><<<grid, 256, SMEM_BYTES>>>(bufB, out,  wr + 1728, wi + 1728);
}

// round 5
// speedup vs baseline: 1.1541x; 1.1541x over previous
#include <cuda_runtime.h>
#include <math.h>

#define HH 640
#define WW 640
#define MHH 40
#define MWW 40
#define NC 8
#define NB 4
#define KPER 400

#define TILE 32
#define PLANE (34*35)                   // 34 rows, stride 35
#define SW_OFF (16*PLANE)               // float offset of weight area (16B aligned)
#define SMEM_FLOATS (16*PLANE + 8*3*8*3*4)
#define SMEM_BYTES  (SMEM_FLOATS*4)

// scratch ping-pong buffers, planar layout [b][c][comp][H][W]
__device__ float g_bufA[NB*NC*2*HH*WW];
__device__ float g_bufB[NB*NC*2*HH*WW];
__device__ float g_bm[NB*MHH*MWW];

// ---------------------------------------------------------------------------
// Mask generation: sigmoid(s_b * w_eff), exact k-th largest (binary search on
// float bit space), binarize. One block per batch.
// ---------------------------------------------------------------------------
__global__ void mask_kernel(const float* __restrict__ my1,
                            const float* __restrict__ wmask,
                            float* __restrict__ out_bin, int write_bin) {
    __shared__ float s_sig[MHH*MWW];
    __shared__ int s_cnt;
    int b = blockIdx.x, tid = threadIdx.x;
    float sb = my1[b];
    for (int i = tid; i < MHH*MWW; i += blockDim.x) {
        int col = i % MWW;
        float wv = (col >= 18 && col < 23) ? 1e7f : wmask[i];
        s_sig[i] = 1.0f / (1.0f + expf(-sb * wv));
    }
    __syncthreads();
    unsigned lo = 0u, hi = 0x3F800001u;   // sigmoid values in (0, 1.0]
    while (hi - lo > 1u) {
        unsigned mid = (lo + hi) >> 1;
        float t = __uint_as_float(mid);
        if (tid == 0) s_cnt = 0;
        __syncthreads();
        int c = 0;
        for (int i = tid; i < MHH*MWW; i += blockDim.x)
            c += (s_sig[i] >= t) ? 1 : 0;
        atomicAdd(&s_cnt, c);
        __syncthreads();
        int tot = s_cnt;
        __syncthreads();
        if (tot >= KPER) lo = mid; else hi = mid;
    }
    float thr = __uint_as_float(lo);
    for (int i = tid; i < MHH*MWW; i += blockDim.x) {
        float v = (s_sig[i] >= thr) ? 1.0f : 0.0f;
        g_bm[b*MHH*MWW + i] = v;
        if (write_bin) out_bin[b*MHH*MWW + i] = v;
    }
}

// ---------------------------------------------------------------------------
// mask_adj = tile(binary_mask) -> d_out
// ---------------------------------------------------------------------------
__global__ void maskadj_kernel(float* __restrict__ out) {
    int idx = blockIdx.x * blockDim.x + threadIdx.x;
    if (idx >= NB*HH*WW) return;
    int w = idx % WW, h = (idx / WW) % HH, b = idx / (HH*WW);
    out[idx] = g_bm[b*MHH*MWW + (h % MHH)*MWW + (w % MWW)];
}

// ---------------------------------------------------------------------------
// Complex 3x3 conv (center tap zeroed) + data consistency, packed f32x2 math.
// IN_X: 1 = read interleaved x and apply mask on load (first iteration),
//       0 = read planar scratch.
// OUT_I: 1 = write interleaved float2 to d_out, 0 = planar scratch.
// Block: 256 thr = 32 cols x 8 row groups; thread: 4 rows x 8 cout (complex).
// ---------------------------------------------------------------------------
template<int IN_X, int OUT_I>
__global__ void __launch_bounds__(256, 2)
conv_kernel(const float* __restrict__ src, float* __restrict__ dst,
            const float* __restrict__ wr_g, const float* __restrict__ wi_g) {
    extern __shared__ float smem[];
    float* s_in = smem;                               // 16 scalar planes
    ulonglong2* s_w = (ulonglong2*)(smem + SW_OFF);   // [ci][kx][co][ky] {wr,wi,-wi,wr}

    const int tid = threadIdx.x;
    const int b  = blockIdx.z;
    const int x0 = blockIdx.x * TILE;
    const int y0 = blockIdx.y * TILE;

    // ---- load input tile (halo 1, zero-padded borders) ----
    if (IN_X) {
        const float2* x2 = (const float2*)src;
        for (int idx = tid; idx < 34*34; idx += 256) {
            int r = idx / 34, c = idx - r*34;
            int gh = y0 - 1 + r, gw = x0 - 1 + c;
            bool inb = (gh >= 0 && gh < HH && gw >= 0 && gw < WW);
            float m = 0.0f;
            if (inb) m = g_bm[b*MHH*MWW + (gh % MHH)*MWW + (gw % MWW)];
            bool live = inb && (m != 0.0f);
#pragma unroll
            for (int c8 = 0; c8 < 8; c8++) {
                float2 v = make_float2(0.0f, 0.0f);
                if (live) v = x2[((b*NC + c8)*HH + gh)*WW + gw];
                s_in[(2*c8  )*PLANE + r*35 + c] = v.x;
                s_in[(2*c8+1)*PLANE + r*35 + c] = v.y;
            }
        }
    } else {
        for (int p = 0; p < 16; p++) {
            const float* sp = src + ((b*NC + (p >> 1))*2 + (p & 1))*HH*WW;
            float* dp = s_in + p*PLANE;
            for (int idx = tid; idx < 34*34; idx += 256) {
                int r = idx / 34, c = idx - r*34;
                int gh = y0 - 1 + r, gw = x0 - 1 + c;
                float v = 0.0f;
                if (gh >= 0 && gh < HH && gw >= 0 && gw < WW) v = sp[gh*WW + gw];
                dp[r*35 + c] = v;
            }
        }
    }
    // ---- build packed weights {wr, wi, -wi, wr}, center tap zeroed ----
    for (int j = tid; j < 576; j += 256) {
        int ky = j % 3, co = (j / 3) & 7, kx = (j / 24) % 3, ci = j / 72;
        int t = ky*3 + kx;
        float vr = 0.0f, vi = 0.0f;
        if (t != 4) {
            vr = wr_g[(co*8 + ci)*9 + t];
            vi = wi_g[(co*8 + ci)*9 + t];
        }
        float4 e; e.x = vr; e.y = vi; e.z = -vi; e.w = vr;
        ((float4*)s_w)[j] = e;
    }
    __syncthreads();

    const int tx = tid & 31, ty = tid >> 5;
    const int row0 = ty * 4;

    unsigned long long acc[8][4];     // packed (accr, acci)
#pragma unroll
    for (int co = 0; co < 8; co++)
#pragma unroll
        for (int p = 0; p < 4; p++) acc[co][p] = 0ull;

#pragma unroll 1
    for (int ci = 0; ci < 8; ci++) {
        const float* pr = s_in + (ci*2)*PLANE + row0*35 + tx;
        const float* pi = pr + PLANE;
#pragma unroll
        for (int kx = 0; kx < 3; kx++) {
            unsigned long long xr2[6], xi2[6];
#pragma unroll
            for (int r = 0; r < 6; r++) {
                float ar = pr[r*35 + kx];
                float ai = pi[r*35 + kx];
                asm("mov.b64 %0, {%1, %1};" : "=l"(xr2[r]) : "f"(ar));
                asm("mov.b64 %0, {%1, %1};" : "=l"(xi2[r]) : "f"(ai));
            }
            const ulonglong2* wp = s_w + ((ci*3 + kx)*8)*3;
#pragma unroll
            for (int co = 0; co < 8; co++) {
                ulonglong2 w0 = wp[co*3 + 0];
                ulonglong2 w1 = wp[co*3 + 1];
                ulonglong2 w2 = wp[co*3 + 2];
#pragma unroll
                for (int p = 0; p < 4; p++) {
                    asm("fma.rn.f32x2 %0, %1, %2, %0;" : "+l"(acc[co][p]) : "l"(xr2[p+0]), "l"(w0.x));
                    asm("fma.rn.f32x2 %0, %1, %2, %0;" : "+l"(acc[co][p]) : "l"(xi2[p+0]), "l"(w0.y));
                    asm("fma.rn.f32x2 %0, %1, %2, %0;" : "+l"(acc[co][p]) : "l"(xr2[p+1]), "l"(w1.x));
                    asm("fma.rn.f32x2 %0, %1, %2, %0;" : "+l"(acc[co][p]) : "l"(xi2[p+1]), "l"(w1.y));
                    asm("fma.rn.f32x2 %0, %1, %2, %0;" : "+l"(acc[co][p]) : "l"(xr2[p+2]), "l"(w2.x));
                    asm("fma.rn.f32x2 %0, %1, %2, %0;" : "+l"(acc[co][p]) : "l"(xi2[p+2]), "l"(w2.y));
                }
            }
        }
    }

    const int ow = x0 + tx;
#pragma unroll
    for (int p = 0; p < 4; p++) {
        const int oh = y0 + row0 + p;
        const float m = g_bm[b*MHH*MWW + (oh % MHH)*MWW + (ow % MWW)];
        const bool keep = (m != 0.0f);
#pragma unroll
        for (int co = 0; co < 8; co++) {
            float vr, vi;
            asm("mov.b64 {%0, %1}, %2;" : "=f"(vr), "=f"(vi) : "l"(acc[co][p]));
            if (keep) {
                // invariant: at m==1, pred_prev == masked x; center is in smem
                vr = s_in[(co*2  )*PLANE + (row0 + p + 1)*35 + (tx + 1)];
                vi = s_in[(co*2+1)*PLANE + (row0 + p + 1)*35 + (tx + 1)];
            }
            if (OUT_I) {
                float2 v; v.x = vr; v.y = vi;
                ((float2*)dst)[((b*NC + co)*HH + oh)*WW + ow] = v;
            } else {
                int basep = ((b*NC + co)*2)*HH*WW + oh*WW + ow;
                dst[basep] = vr;
                dst[basep + HH*WW] = vi;
            }
        }
    }
}

// ---------------------------------------------------------------------------
extern "C" void kernel_launch(void* const* d_in, const int* in_sizes, int n_in,
                              void* d_out, int out_size) {
    const float* x     = (const float*)d_in[0];   // [4,8,640,640,2]
    const float* my1   = (const float*)d_in[1];   // [4,1,1,1]
    const float* wmask = (const float*)d_in[2];   // [1,1,40,40]
    const float* wr    = (const float*)d_in[3];   // [4,8,8,3,3]
    const float* wi    = (const float*)d_in[4];   // [4,8,8,3,3]
    float* out = (float*)d_out;

    void *pA, *pB;
    cudaGetSymbolAddress(&pA, g_bufA);
    cudaGetSymbolAddress(&pB, g_bufB);
    float* bufA = (float*)pA;
    float* bufB = (float*)pB;

    const int PRED = NB*NC*HH*WW*2;
    const int MADJ = NB*HH*WW;
    const int BINM = NB*MHH*MWW;
    int has_extra = (out_size >= PRED + MADJ + BINM) ? 1 : 0;
    float* out_bin = has_extra ? out + PRED + MADJ : nullptr;

    cudaFuncSetAttribute(conv_kernel<1,0>, cudaFuncAttributeMaxDynamicSharedMemorySize, SMEM_BYTES);
    cudaFuncSetAttribute(conv_kernel<0,0>, cudaFuncAttributeMaxDynamicSharedMemorySize, SMEM_BYTES);
    cudaFuncSetAttribute(conv_kernel<0,1>, cudaFuncAttributeMaxDynamicSharedMemorySize, SMEM_BYTES);

    mask_kernel<<<NB, 256>>>(my1, wmask, out_bin, has_extra);
    if (has_extra)
        maskadj_kernel<<<(NB*HH*WW + 255)/256, 256>>>(out + PRED);

    dim3 grid(WW/TILE, HH/TILE, NB);  // 20 x 20 x 4
    conv_kernel<1,0><<<grid, 256, SMEM_BYTES>>>(x,    bufB, wr,        wi);
    conv_kernel<0,0><<<grid, 256, SMEM_BYTES>>>(bufB, bufA, wr + 576,  wi + 576);
    conv_kernel<0,0><<<grid, 256, SMEM_BYTES>>>(bufA, bufB, wr + 1152, wi + 1152);
    conv_kernel<0,1><<<grid, 256, SMEM_BYTES>>>(bufB, out,  wr + 1728, wi + 1728);
}

// round 6
// speedup vs baseline: 1.8185x; 1.5756x over previous
#include <cuda_runtime.h>
#include <math.h>

#define HH 640
#define WW 640
#define MHH 40
#define MWW 40
#define NC 8
#define NB 4
#define KPER 400

#define TILE 32
#define PLANE2 (34*35)                         // float2 units per plane
#define NW_ENTRIES 576                         // 8ci*3kx*8co*3ky
#define SMEM_BYTES (8*PLANE2*8 + NW_ENTRIES*16)  // 76160 + 9216 = 85376

typedef unsigned long long ull;

// scratch ping-pong buffers, interleaved float2 layout [b][c][H][W]
__device__ ull g_bufA[NB*NC*HH*WW];
__device__ ull g_bufB[NB*NC*HH*WW];
__device__ float g_bm[NB*MHH*MWW];

// ---------------------------------------------------------------------------
// Mask: sigmoid(s_b * w_eff), exact 400th-largest via binary search on float
// bits, binarize. One block per batch.
// ---------------------------------------------------------------------------
__global__ void mask_kernel(const float* __restrict__ my1,
                            const float* __restrict__ wmask,
                            float* __restrict__ out_bin, int write_bin) {
    __shared__ float s_sig[MHH*MWW];
    __shared__ int s_cnt;
    int b = blockIdx.x, tid = threadIdx.x;
    float sb = my1[b];
    for (int i = tid; i < MHH*MWW; i += blockDim.x) {
        int col = i % MWW;
        float wv = (col >= 18 && col < 23) ? 1e7f : wmask[i];
        s_sig[i] = 1.0f / (1.0f + expf(-sb * wv));
    }
    __syncthreads();
    unsigned lo = 0u, hi = 0x3F800001u;
    while (hi - lo > 1u) {
        unsigned mid = (lo + hi) >> 1;
        float t = __uint_as_float(mid);
        if (tid == 0) s_cnt = 0;
        __syncthreads();
        int c = 0;
        for (int i = tid; i < MHH*MWW; i += blockDim.x)
            c += (s_sig[i] >= t) ? 1 : 0;
        atomicAdd(&s_cnt, c);
        __syncthreads();
        int tot = s_cnt;
        __syncthreads();
        if (tot >= KPER) lo = mid; else hi = mid;
    }
    float thr = __uint_as_float(lo);
    for (int i = tid; i < MHH*MWW; i += blockDim.x) {
        float v = (s_sig[i] >= thr) ? 1.0f : 0.0f;
        g_bm[b*MHH*MWW + i] = v;
        if (write_bin) out_bin[b*MHH*MWW + i] = v;
    }
}

__global__ void maskadj_kernel(float* __restrict__ out) {
    int idx = blockIdx.x * blockDim.x + threadIdx.x;
    if (idx >= NB*HH*WW) return;
    int w = idx % WW, h = (idx / WW) % HH, b = idx / (HH*WW);
    out[idx] = g_bm[b*MHH*MWW + (h % MHH)*MWW + (w % MWW)];
}

// ---------------------------------------------------------------------------
// Complex 3x3 conv (center zeroed) + data consistency.
// src/dst: interleaved float2 [b][c][H][W] (stored as ull).
// MASK_IN=1: src is raw x; zero where mask==0 during tile load (iteration 1).
// 512 threads: 32 cols x 16 row-groups, 2 rows x 8 cout per thread.
// Math: acc{r,i} += v{r,i}*{wr,wr} + vswap{i,r}*{-wi,wi}   (2 FFMA2/tap)
// ---------------------------------------------------------------------------
template<int MASK_IN>
__global__ void __launch_bounds__(512, 2)
conv_kernel(const ull* __restrict__ src, ull* __restrict__ dst,
            const float* __restrict__ wr_g, const float* __restrict__ wi_g) {
    extern __shared__ float smem[];
    ull* s_in = (ull*)smem;                              // 8 planes of 34x(35) float2
    ulonglong2* s_w = (ulonglong2*)(smem + 8*PLANE2*2);  // 576 x {wr,wr,-wi,wi}

    const int tid = threadIdx.x;
    const int b  = blockIdx.z;
    const int x0 = blockIdx.x * TILE;
    const int y0 = blockIdx.y * TILE;

    // ---- load tile (halo 1, zero-padded) ----
    for (int idx = tid; idx < 34*34; idx += 512) {
        int r = idx / 34, c = idx - r*34;
        int gh = y0 - 1 + r, gw = x0 - 1 + c;
        bool inb = (gh >= 0 && gh < HH && gw >= 0 && gw < WW);
        bool live = inb;
        if (MASK_IN) {
            float m = 0.0f;
            if (inb) m = g_bm[b*MHH*MWW + (gh % MHH)*MWW + (gw % MWW)];
            live = inb && (m != 0.0f);
        }
#pragma unroll
        for (int ci = 0; ci < 8; ci++) {
            ull v = 0ull;
            if (live) v = src[((b*NC + ci)*HH + gh)*WW + gw];
            s_in[ci*PLANE2 + r*35 + c] = v;
        }
    }
    // ---- pack weights {wr, wr, -wi, wi}, center tap zeroed ----
    for (int j = tid; j < NW_ENTRIES; j += 512) {
        int ky = j % 3, co = (j / 3) & 7, kx = (j / 24) % 3, ci = j / 72;
        int t = ky*3 + kx;
        float vr = 0.0f, vi = 0.0f;
        if (t != 4) {
            vr = wr_g[(co*8 + ci)*9 + t];
            vi = wi_g[(co*8 + ci)*9 + t];
        }
        float4 e; e.x = vr; e.y = vr; e.z = -vi; e.w = vi;
        ((float4*)s_w)[j] = e;
    }
    __syncthreads();

    const int tx = tid & 31, ty = tid >> 5;
    const int row0 = ty * 2;

    ull acc[8][2];
#pragma unroll
    for (int co = 0; co < 8; co++) { acc[co][0] = 0ull; acc[co][1] = 0ull; }

#pragma unroll 1
    for (int ci = 0; ci < 8; ci++) {
        const ull* pb = s_in + ci*PLANE2 + row0*35 + tx;
#pragma unroll
        for (int kx = 0; kx < 3; kx++) {
            ull v64[4], vs64[4];
#pragma unroll
            for (int r = 0; r < 4; r++) {
                ull v = pb[r*35 + kx];
                v64[r] = v;
                float ar, ai;
                asm("mov.b64 {%0, %1}, %2;" : "=f"(ar), "=f"(ai) : "l"(v));
                asm("mov.b64 %0, {%1, %2};" : "=l"(vs64[r]) : "f"(ai), "f"(ar));
            }
            const ulonglong2* wq = s_w + ((ci*3 + kx)*8)*3;
#pragma unroll
            for (int co = 0; co < 8; co++) {
                ulonglong2 wa = wq[co*3 + 0];
                ulonglong2 wb = wq[co*3 + 1];
                ulonglong2 wc = wq[co*3 + 2];
                asm("fma.rn.f32x2 %0, %1, %2, %0;" : "+l"(acc[co][0]) : "l"(v64[0]),  "l"(wa.x));
                asm("fma.rn.f32x2 %0, %1, %2, %0;" : "+l"(acc[co][0]) : "l"(vs64[0]), "l"(wa.y));
                asm("fma.rn.f32x2 %0, %1, %2, %0;" : "+l"(acc[co][0]) : "l"(v64[1]),  "l"(wb.x));
                asm("fma.rn.f32x2 %0, %1, %2, %0;" : "+l"(acc[co][0]) : "l"(vs64[1]), "l"(wb.y));
                asm("fma.rn.f32x2 %0, %1, %2, %0;" : "+l"(acc[co][0]) : "l"(v64[2]),  "l"(wc.x));
                asm("fma.rn.f32x2 %0, %1, %2, %0;" : "+l"(acc[co][0]) : "l"(vs64[2]), "l"(wc.y));
                asm("fma.rn.f32x2 %0, %1, %2, %0;" : "+l"(acc[co][1]) : "l"(v64[1]),  "l"(wa.x));
                asm("fma.rn.f32x2 %0, %1, %2, %0;" : "+l"(acc[co][1]) : "l"(vs64[1]), "l"(wa.y));
                asm("fma.rn.f32x2 %0, %1, %2, %0;" : "+l"(acc[co][1]) : "l"(v64[2]),  "l"(wb.x));
                asm("fma.rn.f32x2 %0, %1, %2, %0;" : "+l"(acc[co][1]) : "l"(vs64[2]), "l"(wb.y));
                asm("fma.rn.f32x2 %0, %1, %2, %0;" : "+l"(acc[co][1]) : "l"(v64[3]),  "l"(wc.x));
                asm("fma.rn.f32x2 %0, %1, %2, %0;" : "+l"(acc[co][1]) : "l"(vs64[3]), "l"(wc.y));
            }
        }
    }

    // ---- data consistency + store (interleaved) ----
    const int ow = x0 + tx;
#pragma unroll
    for (int p = 0; p < 2; p++) {
        const int oh = y0 + row0 + p;
        const float m = g_bm[b*MHH*MWW + (oh % MHH)*MWW + (ow % MWW)];
        const bool keep = (m != 0.0f);
#pragma unroll
        for (int co = 0; co < 8; co++) {
            // at m==1 pred_prev == (masked) x; center value is in smem plane co
            ull v = keep ? s_in[co*PLANE2 + (row0 + p + 1)*35 + (tx + 1)]
                         : acc[co][p];
            dst[((b*NC + co)*HH + oh)*WW + ow] = v;
        }
    }
}

// ---------------------------------------------------------------------------
extern "C" void kernel_launch(void* const* d_in, const int* in_sizes, int n_in,
                              void* d_out, int out_size) {
    const ull*   x     = (const ull*)d_in[0];     // [4,8,640,640] float2
    const float* my1   = (const float*)d_in[1];
    const float* wmask = (const float*)d_in[2];
    const float* wr    = (const float*)d_in[3];   // [4,8,8,3,3]
    const float* wi    = (const float*)d_in[4];
    float* out = (float*)d_out;

    void *pA, *pB;
    cudaGetSymbolAddress(&pA, g_bufA);
    cudaGetSymbolAddress(&pB, g_bufB);
    ull* bufA = (ull*)pA;
    ull* bufB = (ull*)pB;

    const int PRED = NB*NC*HH*WW*2;
    const int MADJ = NB*HH*WW;
    const int BINM = NB*MHH*MWW;
    int has_extra = (out_size >= PRED + MADJ + BINM) ? 1 : 0;
    float* out_bin = has_extra ? out + PRED + MADJ : nullptr;

    cudaFuncSetAttribute(conv_kernel<1>, cudaFuncAttributeMaxDynamicSharedMemorySize, SMEM_BYTES);
    cudaFuncSetAttribute(conv_kernel<0>, cudaFuncAttributeMaxDynamicSharedMemorySize, SMEM_BYTES);

    mask_kernel<<<NB, 256>>>(my1, wmask, out_bin, has_extra);
    if (has_extra)
        maskadj_kernel<<<(NB*HH*WW + 255)/256, 256>>>(out + PRED);

    dim3 grid(WW/TILE, HH/TILE, NB);  // 20 x 20 x 4
    conv_kernel<1><<<grid, 512, SMEM_BYTES>>>(x,    bufA, wr,        wi);
    conv_kernel<0><<<grid, 512, SMEM_BYTES>>>(bufA, bufB, wr + 576,  wi + 576);
    conv_kernel<0><<<grid, 512, SMEM_BYTES>>>(bufB, bufA, wr + 1152, wi + 1152);
    conv_kernel<0><<<grid, 512, SMEM_BYTES>>>(bufA, (ull*)out, wr + 1728, wi + 1728);
}

// round 7
// speedup vs baseline: 2.4626x; 1.3542x over previous
#include <cuda_runtime.h>
#include <math.h>

#define HH 640
#define WW 640
#define MHH 40
#define MWW 40
#define NC 8
#define NB 4
#define KPER 400

#define TILE 32
#define PLANE2 (34*35)                 // float2 units per plane
#define SMEM_BYTES (8*PLANE2*8)        // 76160: input planes only

typedef unsigned long long ull;

// scratch ping-pong buffers, interleaved float2 layout [b][c][H][W]
__device__ ull g_bufA[NB*NC*HH*WW];
__device__ ull g_bufB[NB*NC*HH*WW];
__device__ float g_bm[NB*MHH*MWW];
__device__ ulonglong2 g_wpack[4*576];     // packed weights staging

// weights in constant bank: [stage][((ci*3+kx)*8+co)*3+ky] = {wr,wr,-wi,wi}
__constant__ ulonglong2 c_wq[4*576];

// ---------------------------------------------------------------------------
// Pack weights: {wr, wr, -wi, wi} per (stage, ci, kx, co, ky), center zeroed.
// ---------------------------------------------------------------------------
__global__ void prep_weights(const float* __restrict__ wr_g,
                             const float* __restrict__ wi_g) {
    int j = blockIdx.x * blockDim.x + threadIdx.x;
    if (j >= 4*576) return;
    int s = j / 576, r = j % 576;
    int ky = r % 3, co = (r / 3) & 7, kx = (r / 24) % 3, ci = r / 72;
    int t = ky*3 + kx;
    float vr = 0.0f, vi = 0.0f;
    if (t != 4) {
        vr = wr_g[s*576 + (co*8 + ci)*9 + t];
        vi = wi_g[s*576 + (co*8 + ci)*9 + t];
    }
    float4 e; e.x = vr; e.y = vr; e.z = -vi; e.w = vi;
    ((float4*)g_wpack)[j] = e;
}

// ---------------------------------------------------------------------------
// Mask: sigmoid(s_b * w_eff), exact 400th-largest via binary search on float
// bits, binarize. One block per batch.
// ---------------------------------------------------------------------------
__global__ void mask_kernel(const float* __restrict__ my1,
                            const float* __restrict__ wmask,
                            float* __restrict__ out_bin, int write_bin) {
    __shared__ float s_sig[MHH*MWW];
    __shared__ int s_cnt;
    int b = blockIdx.x, tid = threadIdx.x;
    float sb = my1[b];
    for (int i = tid; i < MHH*MWW; i += blockDim.x) {
        int col = i % MWW;
        float wv = (col >= 18 && col < 23) ? 1e7f : wmask[i];
        s_sig[i] = 1.0f / (1.0f + expf(-sb * wv));
    }
    __syncthreads();
    unsigned lo = 0u, hi = 0x3F800001u;
    while (hi - lo > 1u) {
        unsigned mid = (lo + hi) >> 1;
        float t = __uint_as_float(mid);
        if (tid == 0) s_cnt = 0;
        __syncthreads();
        int c = 0;
        for (int i = tid; i < MHH*MWW; i += blockDim.x)
            c += (s_sig[i] >= t) ? 1 : 0;
        atomicAdd(&s_cnt, c);
        __syncthreads();
        int tot = s_cnt;
        __syncthreads();
        if (tot >= KPER) lo = mid; else hi = mid;
    }
    float thr = __uint_as_float(lo);
    for (int i = tid; i < MHH*MWW; i += blockDim.x) {
        float v = (s_sig[i] >= thr) ? 1.0f : 0.0f;
        g_bm[b*MHH*MWW + i] = v;
        if (write_bin) out_bin[b*MHH*MWW + i] = v;
    }
}

__global__ void maskadj_kernel(float* __restrict__ out) {
    int idx = blockIdx.x * blockDim.x + threadIdx.x;
    if (idx >= NB*HH*WW) return;
    int w = idx % WW, h = (idx / WW) % HH, b = idx / (HH*WW);
    out[idx] = g_bm[b*MHH*MWW + (h % MHH)*MWW + (w % MWW)];
}

// ---------------------------------------------------------------------------
// Complex 3x3 conv (center zeroed) + data consistency.
// src/dst: interleaved float2 [b][c][H][W] (stored as ull).
// MASK_IN=1: src is raw x; zero where mask==0 during tile load (iteration 1).
// 512 threads: 32 cols x 16 row-groups, 2 rows x 8 cout per thread.
// Weights from __constant__ (LDC/ULDC port, off the L1 path).
// Math: acc{r,i} += v{r,i}*{wr,wr} + vswap{i,r}*{-wi,wi}   (2 FFMA2/tap)
// ---------------------------------------------------------------------------
template<int MASK_IN>
__global__ void __launch_bounds__(512, 2)
conv_kernel(const ull* __restrict__ src, ull* __restrict__ dst, int stage_off) {
    extern __shared__ float smem[];
    ull* s_in = (ull*)smem;                 // 8 planes of 34x(35) float2

    const int tid = threadIdx.x;
    const int b  = blockIdx.z;
    const int x0 = blockIdx.x * TILE;
    const int y0 = blockIdx.y * TILE;

    // ---- load tile (halo 1, zero-padded) ----
    for (int idx = tid; idx < 34*34; idx += 512) {
        int r = idx / 34, c = idx - r*34;
        int gh = y0 - 1 + r, gw = x0 - 1 + c;
        bool inb = (gh >= 0 && gh < HH && gw >= 0 && gw < WW);
        bool live = inb;
        if (MASK_IN) {
            float m = 0.0f;
            if (inb) m = g_bm[b*MHH*MWW + (gh % MHH)*MWW + (gw % MWW)];
            live = inb && (m != 0.0f);
        }
#pragma unroll
        for (int ci = 0; ci < 8; ci++) {
            ull v = 0ull;
            if (live) v = src[((b*NC + ci)*HH + gh)*WW + gw];
            s_in[ci*PLANE2 + r*35 + c] = v;
        }
    }
    __syncthreads();

    const int tx = tid & 31, ty = tid >> 5;
    const int row0 = ty * 2;

    ull acc[8][2];
#pragma unroll
    for (int co = 0; co < 8; co++) { acc[co][0] = 0ull; acc[co][1] = 0ull; }

#pragma unroll 1
    for (int ci = 0; ci < 8; ci++) {
        const ull* pb = s_in + ci*PLANE2 + row0*35 + tx;
#pragma unroll
        for (int kx = 0; kx < 3; kx++) {
            ull v64[4], vs64[4];
#pragma unroll
            for (int r = 0; r < 4; r++) {
                ull v = pb[r*35 + kx];
                v64[r] = v;
                float ar, ai;
                asm("mov.b64 {%0, %1}, %2;" : "=f"(ar), "=f"(ai) : "l"(v));
                asm("mov.b64 %0, {%1, %2};" : "=l"(vs64[r]) : "f"(ai), "f"(ar));
            }
            const int cb = stage_off + ((ci*3 + kx)*8)*3;
#pragma unroll
            for (int co = 0; co < 8; co++) {
                ulonglong2 wa = c_wq[cb + co*3 + 0];
                ulonglong2 wb = c_wq[cb + co*3 + 1];
                ulonglong2 wc = c_wq[cb + co*3 + 2];
                asm("fma.rn.f32x2 %0, %1, %2, %0;" : "+l"(acc[co][0]) : "l"(v64[0]),  "l"(wa.x));
                asm("fma.rn.f32x2 %0, %1, %2, %0;" : "+l"(acc[co][0]) : "l"(vs64[0]), "l"(wa.y));
                asm("fma.rn.f32x2 %0, %1, %2, %0;" : "+l"(acc[co][0]) : "l"(v64[1]),  "l"(wb.x));
                asm("fma.rn.f32x2 %0, %1, %2, %0;" : "+l"(acc[co][0]) : "l"(vs64[1]), "l"(wb.y));
                asm("fma.rn.f32x2 %0, %1, %2, %0;" : "+l"(acc[co][0]) : "l"(v64[2]),  "l"(wc.x));
                asm("fma.rn.f32x2 %0, %1, %2, %0;" : "+l"(acc[co][0]) : "l"(vs64[2]), "l"(wc.y));
                asm("fma.rn.f32x2 %0, %1, %2, %0;" : "+l"(acc[co][1]) : "l"(v64[1]),  "l"(wa.x));
                asm("fma.rn.f32x2 %0, %1, %2, %0;" : "+l"(acc[co][1]) : "l"(vs64[1]), "l"(wa.y));
                asm("fma.rn.f32x2 %0, %1, %2, %0;" : "+l"(acc[co][1]) : "l"(v64[2]),  "l"(wb.x));
                asm("fma.rn.f32x2 %0, %1, %2, %0;" : "+l"(acc[co][1]) : "l"(vs64[2]), "l"(wb.y));
                asm("fma.rn.f32x2 %0, %1, %2, %0;" : "+l"(acc[co][1]) : "l"(v64[3]),  "l"(wc.x));
                asm("fma.rn.f32x2 %0, %1, %2, %0;" : "+l"(acc[co][1]) : "l"(vs64[3]), "l"(wc.y));
            }
        }
    }

    // ---- data consistency + store (interleaved) ----
    const int ow = x0 + tx;
#pragma unroll
    for (int p = 0; p < 2; p++) {
        const int oh = y0 + row0 + p;
        const float m = g_bm[b*MHH*MWW + (oh % MHH)*MWW + (ow % MWW)];
        const bool keep = (m != 0.0f);
#pragma unroll
        for (int co = 0; co < 8; co++) {
            // at m==1 pred_prev == (masked) x; center value is in smem plane co
            ull v = keep ? s_in[co*PLANE2 + (row0 + p + 1)*35 + (tx + 1)]
                         : acc[co][p];
            dst[((b*NC + co)*HH + oh)*WW + ow] = v;
        }
    }
}

// ---------------------------------------------------------------------------
extern "C" void kernel_launch(void* const* d_in, const int* in_sizes, int n_in,
                              void* d_out, int out_size) {
    const ull*   x     = (const ull*)d_in[0];     // [4,8,640,640] float2
    const float* my1   = (const float*)d_in[1];
    const float* wmask = (const float*)d_in[2];
    const float* wr    = (const float*)d_in[3];   // [4,8,8,3,3]
    const float* wi    = (const float*)d_in[4];
    float* out = (float*)d_out;

    void *pA, *pB, *pW;
    cudaGetSymbolAddress(&pA, g_bufA);
    cudaGetSymbolAddress(&pB, g_bufB);
    cudaGetSymbolAddress(&pW, g_wpack);
    ull* bufA = (ull*)pA;
    ull* bufB = (ull*)pB;

    const int PRED = NB*NC*HH*WW*2;
    const int MADJ = NB*HH*WW;
    const int BINM = NB*MHH*MWW;
    int has_extra = (out_size >= PRED + MADJ + BINM) ? 1 : 0;
    float* out_bin = has_extra ? out + PRED + MADJ : nullptr;

    cudaFuncSetAttribute(conv_kernel<1>, cudaFuncAttributeMaxDynamicSharedMemorySize, SMEM_BYTES);
    cudaFuncSetAttribute(conv_kernel<0>, cudaFuncAttributeMaxDynamicSharedMemorySize, SMEM_BYTES);

    prep_weights<<<9, 256>>>(wr, wi);
    cudaMemcpyToSymbolAsync(c_wq, pW, 4*576*sizeof(ulonglong2), 0,
                            cudaMemcpyDeviceToDevice, 0);
    mask_kernel<<<NB, 256>>>(my1, wmask, out_bin, has_extra);
    if (has_extra)
        maskadj_kernel<<<(NB*HH*WW + 255)/256, 256>>>(out + PRED);

    dim3 grid(WW/TILE, HH/TILE, NB);  // 20 x 20 x 4
    conv_kernel<1><<<grid, 512, SMEM_BYTES>>>(x,    bufA, 0);
    conv_kernel<0><<<grid, 512, SMEM_BYTES>>>(bufA, bufB, 576);
    conv_kernel<0><<<grid, 512, SMEM_BYTES>>>(bufB, bufA, 1152);
    conv_kernel<0><<<grid, 512, SMEM_BYTES>>>(bufA, (ull*)out, 1728);
}